// round 16
// baseline (speedup 1.0000x reference)
#include <cuda_runtime.h>
#include <cstdint>

#define ND 4096
#define BM 128
#define BN 128
#define BK 32
#define KGEMM 128
#define KIT (KGEMM / BK)        // 4
#define NJOBS 1024

#define STAGE_BYTES ((BM + BN) * BK * 4)          // 32 KB
#define SMEM_TOTAL (3 * STAGE_BYTES)              // 96 KB -> 2 CTAs/SM

// Bases [128][128] (64KB each; L1/L2-resident)
__device__ __align__(1024) float g_Bc7 [(size_t)128 * 128]; // cos(pi(2r+1)(2t+1)/512)
__device__ __align__(1024) float g_Bs7 [(size_t)128 * 128]; // sin(pi(2r+1)(2t+1)/512)
__device__ __align__(1024) float g_Cee8[(size_t)128 * 128]; // cos(pi(2r+1)t/256)
// 32 leaf A-buffers [4096][128]
__device__ __align__(1024) float g_L[32][(size_t)ND * 128];
// 30 leaf GEMM outputs [128][4096]
__device__ __align__(1024) float g_P[30][(size_t)128 * ND];
// Intermediate
__device__ __align__(1024) float g_Yt [(size_t)ND * ND];

// ---------------------------------------------------------------- helpers
__device__ __forceinline__ uint32_t smem_u32(const void* p) {
    uint32_t a;
    asm("{ .reg .u64 t; cvta.to.shared.u64 t, %1; cvt.u32.u64 %0, t; }"
        : "=r"(a) : "l"(p));
    return a;
}
__device__ __forceinline__ float tf32_rna(float x) {
    uint32_t b;
    asm("cvt.rna.tf32.f32 %0, %1;" : "=r"(b) : "f"(x));
    return __uint_as_float(b);
}
__device__ __forceinline__ uint32_t swz(uint32_t off) {
    return off ^ ((off >> 3) & 0x70);  // SW128 (Swizzle<3,4,3>), 128B rows
}
__device__ __forceinline__ void cp16(uint32_t sdst, const float* gsrc) {
    asm volatile("cp.async.cg.shared.global [%0], [%1], 16;"
                 :: "r"(sdst), "l"(__cvta_generic_to_global(gsrc)) : "memory");
}
__device__ __forceinline__ void cp_commit() {
    asm volatile("cp.async.commit_group;" ::: "memory");
}
template <int N>
__device__ __forceinline__ void cp_wait() {
    asm volatile("cp.async.wait_group %0;" :: "n"(N) : "memory");
}
__device__ __forceinline__ void ldsm4(uint32_t* r, uint32_t a) {
    asm volatile("ldmatrix.sync.aligned.m8n8.x4.shared.b16 {%0,%1,%2,%3}, [%4];"
                 : "=r"(r[0]), "=r"(r[1]), "=r"(r[2]), "=r"(r[3]) : "r"(a));
}
__device__ __forceinline__ void mma1688(float* d, const uint32_t* a, const uint32_t* b) {
    asm volatile(
        "mma.sync.aligned.m16n8k8.row.col.f32.tf32.tf32.f32 "
        "{%0,%1,%2,%3}, {%4,%5,%6,%7}, {%8,%9}, {%0,%1,%2,%3};"
        : "+f"(d[0]), "+f"(d[1]), "+f"(d[2]), "+f"(d[3])
        : "r"(a[0]), "r"(a[1]), "r"(a[2]), "r"(a[3]), "r"(b[0]), "r"(b[1]));
}
__device__ __forceinline__ float2 f2c2(float a, float2 x, float b, float2 y) {
    float2 r; r.x = a * x.x + b * y.x; r.y = a * x.y + b * y.y; return r;
}
__device__ __forceinline__ float2 f2s(float a, float2 x) {
    float2 r; r.x = a * x.x; r.y = a * x.y; return r;
}

// ---------------------------------------------------------------- bases (device fn)
__device__ void gen_bases_block(int t, int tid) {
    if (tid >= 32) return;
    int q  = tid;                         // 0..31
    int r0 = q << 2;
    int kt = 2 * t + 1;
    int b  = (2 * r0 + 1) * kt, st = 2 * kt;
    const float s = 1.0f / 512.0f;
    float4 rc, rs;
    rc.x = tf32_rna(cospif((float)((b          ) & 1023) * s));
    rc.y = tf32_rna(cospif((float)((b +     st) & 1023) * s));
    rc.z = tf32_rna(cospif((float)((b + 2 * st) & 1023) * s));
    rc.w = tf32_rna(cospif((float)((b + 3 * st) & 1023) * s));
    rs.x = tf32_rna(sinpif((float)((b          ) & 1023) * s));
    rs.y = tf32_rna(sinpif((float)((b +     st) & 1023) * s));
    rs.z = tf32_rna(sinpif((float)((b + 2 * st) & 1023) * s));
    rs.w = tf32_rna(sinpif((float)((b + 3 * st) & 1023) * s));
    ((float4*)g_Bc7)[(size_t)t * 32 + q] = rc;
    ((float4*)g_Bs7)[(size_t)t * 32 + q] = rs;
    int be = (2 * r0 + 1) * t, se = 2 * t;
    const float s2 = 1.0f / 256.0f;
    float4 re;
    re.x = tf32_rna(cospif((float)((be          ) & 511) * s2));
    re.y = tf32_rna(cospif((float)((be +     se) & 511) * s2));
    re.z = tf32_rna(cospif((float)((be + 2 * se) & 511) * s2));
    re.w = tf32_rna(cospif((float)((be + 3 * se) & 511) * s2));
    ((float4*)g_Cee8)[(size_t)t * 32 + q] = re;
}

// ---------------------------------------------------------------- fold
// Blocks [0,4096): fold row. Blocks [4096,4224): generate bases (pass A only).
struct FoldOut { float* L[32]; };

__global__ void __launch_bounds__(256) fold_kernel(
    const float* __restrict__ src, FoldOut fo, int with_gen)
{
    __shared__ float X[4096];
    __shared__ float A1[2048];
    __shared__ float SS[2048];
    __shared__ float S[1024], D[1024], A2[1024], S2[1024];
    __shared__ float MID[16][256];
    int tid = threadIdx.x;
    if (with_gen && blockIdx.x >= ND) {
        gen_bases_block((int)blockIdx.x - ND, tid);
        return;
    }
    size_t row = blockIdx.x;
    const float4* rp = (const float4*)(src + row * ND);

    #pragma unroll
    for (int i = 0; i < 4; i++)
        ((float4*)X)[tid + i * 256] = rp[tid + i * 256];
    __syncthreads();

    #pragma unroll
    for (int i = 0; i < 8; i++) {
        int j = tid + i * 256;
        float a = X[j], b = X[4095 - j];
        A1[j] = a - b;
        SS[j] = a + b;
    }
    __syncthreads();

    #pragma unroll
    for (int i = 0; i < 4; i++) {
        int r = tid + i * 256;
        float p = A1[2 * r], q = A1[2 * r + 1];
        S[r] = p + q;  D[r] = p - q;
        float u = SS[r], v = SS[2047 - r];
        A2[r] = u - v;  S2[r] = u + v;
    }
    __syncthreads();

    {
        int r = tid;           // 0..255
        float s0 = S[4*r], s1 = S[4*r+1], s2 = S[4*r+2], s3 = S[4*r+3];
        MID[0][r] = (s0 + s1) + (s2 + s3);
        MID[1][r] = (s0 + s1) - (s2 + s3);
        float t0 = S[1020-4*r], t1 = S[1021-4*r], t2 = S[1022-4*r], t3 = S[1023-4*r];
        MID[2][r] = (t2 - t3) + (t0 - t1);
        MID[3][r] = (t2 - t3) - (t0 - t1);
        float u0 = D[1020-4*r], u1 = D[1021-4*r], u2 = D[1022-4*r], u3 = D[1023-4*r];
        MID[4][r] = (u3 + u2) + (u1 + u0);
        MID[5][r] = (u3 + u2) - (u1 + u0);
        float d0 = D[4*r], d1 = D[4*r+1], d2 = D[4*r+2], d3 = D[4*r+3];
        MID[6][r] = (d1 - d0) + (d3 - d2);
        MID[7][r] = (d1 - d0) - (d3 - d2);
        float a0 = A2[4*r], a1 = A2[4*r+1], a2 = A2[4*r+2], a3 = A2[4*r+3];
        MID[8][r] = (a0 + a1) + (a2 + a3);
        MID[9][r] = (a0 + a1) - (a2 + a3);
        float b0 = A2[1020-4*r], b1 = A2[1021-4*r], b2 = A2[1022-4*r], b3 = A2[1023-4*r];
        MID[10][r] = (b2 - b3) + (b0 - b1);
        MID[11][r] = (b2 - b3) - (b0 - b1);
        float w0 = S2[2*r]   - S2[1023-2*r];
        float w1 = S2[2*r+1] - S2[1022-2*r];
        MID[12][r] = w0 + w1;
        MID[13][r] = w0 - w1;
        float e1 = S2[r] + S2[1023-r];
        float e2 = S2[511-r] + S2[512+r];
        MID[14][r] = e1 + e2;
        MID[15][r] = e1 - e2;
    }
    __syncthreads();

    {
        int g  = tid >> 7;
        int rho = tid & 127;
        #pragma unroll
        for (int mm = 0; mm < 8; mm++) {
            int m = g * 8 + mm;
            float p, q;
            if (m == 14) { p = MID[14][rho]; q = MID[14][255 - rho]; }
            else         { p = MID[m][2 * rho]; q = MID[m][2 * rho + 1]; }
            fo.L[2 * m][row * 128 + rho]     = tf32_rna(p + q);
            fo.L[2 * m + 1][row * 128 + rho] = tf32_rna(p - q);
        }
    }
}

// ---------------------------------------------------------------- rotate (R15 validated)
struct RotParams { const float* P[30]; float* out; };

__global__ void __launch_bounds__(256) rotate_kernel(RotParams rp) {
    int tau = blockIdx.y;                             // 0..127
    int c2 = blockIdx.x * 256 + threadIdx.x;          // 0..2047 (float2 cols)
    size_t off = (size_t)tau * 2048 + c2;
    float c4 = cospif((float)(2 * tau + 1) * (1.0f / 1024.0f));
    float s4 = sinpif((float)(2 * tau + 1) * (1.0f / 1024.0f));
    float* out = rp.out;

    float2 PC[7][2], PS[7][2];
    #pragma unroll
    for (int j = 0; j < 7; j++) {
        float2 a = ((const float2*)rp.P[4 * j])[off];
        float2 b = ((const float2*)rp.P[4 * j + 1])[off];
        float2 c = ((const float2*)rp.P[4 * j + 2])[off];
        float2 d = ((const float2*)rp.P[4 * j + 3])[off];
        PC[j][0] = f2c2( c4, a, s4, b);
        PC[j][1] = f2c2(-s4, a, c4, b);
        PS[j][0] = f2c2( c4, c, -s4, d);
        PS[j][1] = f2c2( s4, c,  c4, d);
    }
    {
        float2 e0 = ((const float2*)rp.P[28])[off];
        float2 e1 = ((const float2*)rp.P[29])[off];
        ((float2*)(out + (size_t)(16 * tau + 8) * ND))[c2]         = f2c2( c4, e0, s4, e1);
        ((float2*)(out + (size_t)(16 * (255 - tau) + 8) * ND))[c2] = f2c2(-s4, e0, c4, e1);
    }

    #pragma unroll
    for (int h4 = 0; h4 < 2; h4++) {
        int t3 = h4 ? (255 - tau) : tau;
        float2 p0 = PC[0][h4], q0 = PS[0][h4];
        float2 p1 = PC[1][h4], q1 = PS[1][h4];
        float2 p2 = PC[2][h4], q2 = PS[2][h4];
        float2 p3 = PC[3][h4], q3 = PS[3][h4];
        float2 p4 = PC[4][h4], q4 = PS[4][h4];
        float2 p5 = PC[5][h4], q5 = PS[5][h4];
        float2 p7 = PC[6][h4], q7 = PS[6][h4];

        float c3 = cospif((float)(2 * t3 + 1) * (1.0f / 2048.0f));
        float s3 = sinpif((float)(2 * t3 + 1) * (1.0f / 2048.0f));
        float sg3 = (t3 & 1) ? -1.0f : 1.0f;

        float2 Scc_a = f2c2( c3, p0, s3, q0), Scc_b = f2c2(-s3, p0, c3, q0);
        float2 D1a   = f2c2( c3, p1, s3, q1), D1b   = f2c2(-s3, p1, c3, q1);
        float2 Scd_a = f2s( sg3, D1a),        Scd_b = f2s(-sg3, D1b);
        float2 Sdc_a = f2c2( c3, p2, s3, q2), Sdc_b = f2c2(-s3, p2, c3, q2);
        float2 D3a   = f2c2( c3, p3, s3, q3), D3b   = f2c2(-s3, p3, c3, q3);
        float2 Sdd_a = f2s( sg3, D3a),        Sdd_b = f2s(-sg3, D3b);
        float2 O2c_a = f2c2( c3, p4, s3, q4), O2c_b = f2c2(-s3, p4, c3, q4);
        float2 D5a   = f2c2( c3, p5, s3, q5), D5b   = f2c2(-s3, p5, c3, q5);
        float2 O2d_a = f2s( sg3, D5a),        O2d_b = f2s(-sg3, D5b);

        ((float2*)(out + (size_t)(8 * t3 + 4) * ND))[c2]    = f2c2( c3, p7, s3, q7);
        ((float2*)(out + (size_t)(4092 - 8 * t3) * ND))[c2] = f2c2(-s3, p7, c3, q7);

        #pragma unroll
        for (int h = 0; h < 2; h++) {
            int sg = h ? (511 - t3) : t3;
            float2 vScc = h ? Scc_b : Scc_a, vScd = h ? Scd_b : Scd_a;
            float2 vSdc = h ? Sdc_b : Sdc_a, vSdd = h ? Sdd_b : Sdd_a;
            float2 vO2c = h ? O2c_b : O2c_a, vO2d = h ? O2d_b : O2d_a;
            float c2r = cospif((float)(2 * sg + 1) * (1.0f / 4096.0f));
            float s2r = sinpif((float)(2 * sg + 1) * (1.0f / 4096.0f));
            float c1t = cospif((float)(2 * sg + 1) * (1.0f / 8192.0f));
            float s1t = sinpif((float)(2 * sg + 1) * (1.0f / 8192.0f));
            float c1m = cospif((float)(2047 - 2 * sg) * (1.0f / 8192.0f));
            float s1m = sinpif((float)(2047 - 2 * sg) * (1.0f / 8192.0f));
            float sgn = (sg & 1) ? -1.0f : 1.0f;
            float2 Sct = f2c2( c2r, vScc, s2r, vScd);
            float2 Scm = f2c2(-s2r, vScc, c2r, vScd);
            float2 Drt = f2c2( c2r, vSdc, s2r, vSdd);
            float2 Drm = f2c2(-s2r, vSdc, c2r, vSdd);
            float2 Sdt = f2s( sgn, Drt);
            float2 Sdm = f2s(-sgn, Drm);
            ((float2*)(out + (size_t)(2 * sg + 1) * ND))[c2]    = f2c2( c1t, Sct, s1t, Sdt);
            ((float2*)(out + (size_t)(4095 - 2 * sg) * ND))[c2] = f2c2(-s1t, Sct, c1t, Sdt);
            ((float2*)(out + (size_t)(2047 - 2 * sg) * ND))[c2] = f2c2( c1m, Scm, s1m, Sdm);
            ((float2*)(out + (size_t)(2049 + 2 * sg) * ND))[c2] = f2c2(-s1m, Scm, c1m, Sdm);
            ((float2*)(out + (size_t)(4 * sg + 2) * ND))[c2]    = f2c2( c2r, vO2c, s2r, vO2d);
            ((float2*)(out + (size_t)(4094 - 4 * sg) * ND))[c2] = f2c2(-s2r, vO2c, c2r, vO2d);
        }
    }
}

// ---------------------------------------------------------------- GEMM
// Persistent: grid = 2*SMs. CTA b handles jobs b, b+G, ... (1024 jobs).
// Flat t counter: job = b + (t>>2)*G, k-slice = t&3. 3-stage cp.async ring
// streams across job boundaries. Epilogue = direct transposed STG.32
// (32B-sector coalesced), no SMEM, no barriers -> overlaps next job's loads.
struct GemmParams {
    const float* A[32];
    const float* B[32];
    float*       O[32];
};

__global__ void __launch_bounds__(256, 2) dct_gemm_kernel(GemmParams p) {
    extern __shared__ __align__(1024) char smem[];
    uint32_t sb = smem_u32(smem);
    int tid = threadIdx.x;
    int wid = tid >> 5, lane = tid & 31;
    int G = gridDim.x;
    int bid = blockIdx.x;
    if (bid >= NJOBS) return;

    int njobs = (NJOBS - 1 - bid) / G + 1;
    int total_t = njobs * KIT;

    int crow = tid >> 3, cch = tid & 7;
    uint32_t sA = swz((uint32_t)(crow * 128 + cch * 16));

    auto issue = [&](int t) {
        int jt = t >> 2, kk = t & 3;
        int job = bid + jt * G;
        int bi = job >> 5, mb = job & 31;
        const float* Ag = p.A[bi] + (size_t)(mb * BM + crow) * KGEMM + cch * 4 + kk * BK;
        const float* Bg = p.B[bi] + (size_t)crow * KGEMM + cch * 4 + kk * BK;
        uint32_t base = sb + (uint32_t)(t % 3) * STAGE_BYTES;
        #pragma unroll
        for (int q = 0; q < 4; q++) {
            uint32_t so = sA + q * 32 * 128;
            cp16(base + so,            Ag + (size_t)(q * 32) * KGEMM);
            cp16(base + BM * 128 + so, Bg + (size_t)(q * 32) * KGEMM);
        }
    };

    issue(0); cp_commit();
    if (total_t > 1) issue(1);
    cp_commit();

    int WM = (wid >> 1) * 32;
    int WN = (wid & 1) * 64;

    float d[2][8][4];
    #pragma unroll
    for (int mt = 0; mt < 2; mt++)
        #pragma unroll
        for (int nt = 0; nt < 8; nt++)
            #pragma unroll
            for (int j = 0; j < 4; j++) d[mt][nt][j] = 0.0f;

    uint32_t aoff = (uint32_t)((lane & 15) * 128 + (lane >> 4) * 16);
    uint32_t boff = (uint32_t)(((lane & 7) + ((lane >> 4) << 3)) * 128
                               + ((lane >> 3) & 1) * 16);
    int g = lane >> 2, tig = lane & 3;

    #pragma unroll 1
    for (int t = 0; t < total_t; t++) {
        cp_wait<1>();
        __syncthreads();
        if (t + 2 < total_t) issue(t + 2);
        cp_commit();

        uint32_t Ab = sb + (uint32_t)(t % 3) * STAGE_BYTES;
        uint32_t Bb = Ab + BM * 128;

        #pragma unroll
        for (int ks = 0; ks < 4; ks++) {
            uint32_t a0[4], a1r[4], bfr[2][4];
            ldsm4(a0,  Ab + swz((uint32_t)(WM * 128)        + aoff + ks * 32));
            ldsm4(a1r, Ab + swz((uint32_t)((WM + 16) * 128) + aoff + ks * 32));
            ldsm4(bfr[0], Bb + swz((uint32_t)(WN * 128)        + boff + ks * 32));
            ldsm4(bfr[1], Bb + swz((uint32_t)((WN + 16) * 128) + boff + ks * 32));
            #pragma unroll
            for (int nt = 0; nt < 4; nt++) {
                const uint32_t* bb = &bfr[nt >> 1][(nt & 1) * 2];
                mma1688(d[0][nt], a0, bb);
                mma1688(d[1][nt], a1r, bb);
            }
            ldsm4(bfr[0], Bb + swz((uint32_t)((WN + 32) * 128) + boff + ks * 32));
            ldsm4(bfr[1], Bb + swz((uint32_t)((WN + 48) * 128) + boff + ks * 32));
            #pragma unroll
            for (int nt = 0; nt < 4; nt++) {
                const uint32_t* bb = &bfr[nt >> 1][(nt & 1) * 2];
                mma1688(d[0][nt + 4], a0, bb);
                mma1688(d[1][nt + 4], a1r, bb);
            }
        }

        if ((t & 3) == 3) {
            // direct transposed epilogue: no SMEM, no barriers.
            int job = bid + (t >> 2) * G;
            int bi = job >> 5, mb = job & 31;
            int rstride = (bi >= 28 && bi <= 29) ? 32 : 1;
            int roff    = (bi == 29) ? 16 : 0;
            float* O = p.O[bi] + (size_t)roff * ND + mb * BM;
            #pragma unroll
            for (int mt = 0; mt < 2; mt++) {
                int m = WM + mt * 16 + g;
                #pragma unroll
                for (int nt = 0; nt < 8; nt++) {
                    int n = WN + nt * 8 + 2 * tig;
                    size_t r0 = (size_t)(rstride * n) * ND;
                    size_t r1 = (size_t)(rstride * (n + 1)) * ND;
                    O[r0 + m]     = d[mt][nt][0];
                    O[r1 + m]     = d[mt][nt][1];
                    O[r0 + m + 8] = d[mt][nt][2];
                    O[r1 + m + 8] = d[mt][nt][3];
                    d[mt][nt][0] = 0.0f; d[mt][nt][1] = 0.0f;
                    d[mt][nt][2] = 0.0f; d[mt][nt][3] = 0.0f;
                }
            }
        }
    }
    cp_wait<0>();
}

// ---------------------------------------------------------------- host
extern "C" void kernel_launch(void* const* d_in, const int* in_sizes, int n_in,
                              void* d_out, int out_size) {
    void *pBc7, *pBs7, *pCee8, *pYt;
    void *pL[32], *pP[30];
    cudaGetSymbolAddress(&pBc7,  g_Bc7);
    cudaGetSymbolAddress(&pBs7,  g_Bs7);
    cudaGetSymbolAddress(&pCee8, g_Cee8);
    cudaGetSymbolAddress(&pYt,   g_Yt);
    {
        void* base;
        cudaGetSymbolAddress(&base, g_L);
        for (int i = 0; i < 32; i++)
            pL[i] = (char*)base + (size_t)i * ND * 128 * sizeof(float);
        cudaGetSymbolAddress(&base, g_P);
        for (int i = 0; i < 30; i++)
            pP[i] = (char*)base + (size_t)i * 128 * ND * sizeof(float);
    }

    int dev = 0, sms = 148;
    cudaGetDevice(&dev);
    cudaDeviceGetAttribute(&sms, cudaDevAttrMultiProcessorCount, dev);
    int grid_g = 2 * sms;
    if (grid_g > NJOBS) grid_g = NJOBS;

    cudaFuncSetAttribute(dct_gemm_kernel,
                         cudaFuncAttributeMaxDynamicSharedMemorySize, SMEM_TOTAL);

    FoldOut fo;
    for (int i = 0; i < 32; i++) fo.L[i] = (float*)pL[i];

    GemmParams gp;
    for (int bi = 0; bi < 32; bi++) {
        gp.A[bi] = (const float*)pL[bi];
        int m = bi >> 1, isd = bi & 1;
        const void* Bp;
        if (m == 14)      Bp = isd ? pBc7 : pCee8;
        else if (m == 15) Bp = isd ? pBs7 : pBc7;
        else if ((m & 1) == 0) Bp = isd ? pBs7 : pBc7;
        else                   Bp = isd ? pBc7 : pBs7;
        gp.B[bi] = (const float*)Bp;
    }
    for (int bi = 0; bi < 28; bi++) gp.O[bi] = (float*)pP[bi];
    gp.O[30] = (float*)pP[28];
    gp.O[31] = (float*)pP[29];

    RotParams rp;
    for (int i = 0; i < 30; i++) rp.P[i] = (const float*)pP[i];

    // ---- Pass A: x -> Yt[v][i]   (fold also generates bases: +128 blocks)
    fold_kernel<<<ND + 128, 256>>>((const float*)d_in[0], fo, 1);
    gp.O[28] = (float*)pYt;  gp.O[29] = (float*)pYt;
    dct_gemm_kernel<<<grid_g, 256, SMEM_TOTAL>>>(gp);
    rp.out = (float*)pYt;
    rotate_kernel<<<dim3(8, 128), 256>>>(rp);

    // ---- Pass B: Yt -> out[u][v]
    fold_kernel<<<ND, 256>>>((const float*)pYt, fo, 0);
    gp.O[28] = (float*)d_out;  gp.O[29] = (float*)d_out;
    dct_gemm_kernel<<<grid_g, 256, SMEM_TOTAL>>>(gp);
    rp.out = (float*)d_out;
    rotate_kernel<<<dim3(8, 128), 256>>>(rp);
}

// round 17
// speedup vs baseline: 1.1058x; 1.1058x over previous
#include <cuda_runtime.h>
#include <cstdint>

#define ND 4096
#define BM 128
#define BN 128
#define BK 32
#define KGEMM 128
#define KIT (KGEMM / BK)        // 4
#define STAGES 3

#define STAGE_BYTES ((BM + BN) * BK * 4)          // 32 KB
#define SMEM_TOTAL (STAGES * STAGE_BYTES)         // 96 KB -> 2 CTAs/SM

// Bases [128][128] (64KB each; L1/L2-resident)
__device__ __align__(1024) float g_Bc7 [(size_t)128 * 128]; // cos(pi(2r+1)(2t+1)/512)
__device__ __align__(1024) float g_Bs7 [(size_t)128 * 128]; // sin(pi(2r+1)(2t+1)/512)
__device__ __align__(1024) float g_Cee8[(size_t)128 * 128]; // cos(pi(2r+1)t/256)
// 32 leaf A-buffers [4096][128]
__device__ __align__(1024) float g_L[32][(size_t)ND * 128];
// 30 leaf GEMM outputs [128][4096]
__device__ __align__(1024) float g_P[30][(size_t)128 * ND];
// Intermediate
__device__ __align__(1024) float g_Yt [(size_t)ND * ND];

// ---------------------------------------------------------------- helpers
__device__ __forceinline__ uint32_t smem_u32(const void* p) {
    uint32_t a;
    asm("{ .reg .u64 t; cvta.to.shared.u64 t, %1; cvt.u32.u64 %0, t; }"
        : "=r"(a) : "l"(p));
    return a;
}
__device__ __forceinline__ float tf32_rna(float x) {
    uint32_t b;
    asm("cvt.rna.tf32.f32 %0, %1;" : "=r"(b) : "f"(x));
    return __uint_as_float(b);
}
__device__ __forceinline__ uint32_t swz(uint32_t off) {
    return off ^ ((off >> 3) & 0x70);  // SW128 (Swizzle<3,4,3>), 128B rows
}
__device__ __forceinline__ void cp16(uint32_t sdst, const float* gsrc) {
    asm volatile("cp.async.cg.shared.global [%0], [%1], 16;"
                 :: "r"(sdst), "l"(__cvta_generic_to_global(gsrc)) : "memory");
}
__device__ __forceinline__ void cp_commit() {
    asm volatile("cp.async.commit_group;" ::: "memory");
}
template <int N>
__device__ __forceinline__ void cp_wait() {
    asm volatile("cp.async.wait_group %0;" :: "n"(N) : "memory");
}
__device__ __forceinline__ void ldsm4(uint32_t* r, uint32_t a) {
    asm volatile("ldmatrix.sync.aligned.m8n8.x4.shared.b16 {%0,%1,%2,%3}, [%4];"
                 : "=r"(r[0]), "=r"(r[1]), "=r"(r[2]), "=r"(r[3]) : "r"(a));
}
__device__ __forceinline__ void mma1688(float* d, const uint32_t* a, const uint32_t* b) {
    asm volatile(
        "mma.sync.aligned.m16n8k8.row.col.f32.tf32.tf32.f32 "
        "{%0,%1,%2,%3}, {%4,%5,%6,%7}, {%8,%9}, {%0,%1,%2,%3};"
        : "+f"(d[0]), "+f"(d[1]), "+f"(d[2]), "+f"(d[3])
        : "r"(a[0]), "r"(a[1]), "r"(a[2]), "r"(a[3]), "r"(b[0]), "r"(b[1]));
}
__device__ __forceinline__ float2 f2c2(float a, float2 x, float b, float2 y) {
    float2 r; r.x = a * x.x + b * y.x; r.y = a * x.y + b * y.y; return r;
}
__device__ __forceinline__ float2 f2s(float a, float2 x) {
    float2 r; r.x = a * x.x; r.y = a * x.y; return r;
}

// ---------------------------------------------------------------- bases
__global__ void gen_bases_kernel(float4* __restrict__ Bc4, float4* __restrict__ Bs4,
                                 float4* __restrict__ Ce4) {
    int t  = blockIdx.y;                  // 0..127
    int q  = threadIdx.x;                 // 0..31
    int r0 = q << 2;
    int kt = 2 * t + 1;
    int b  = (2 * r0 + 1) * kt, st = 2 * kt;
    const float s = 1.0f / 512.0f;
    float4 rc, rs;
    rc.x = tf32_rna(cospif((float)((b          ) & 1023) * s));
    rc.y = tf32_rna(cospif((float)((b +     st) & 1023) * s));
    rc.z = tf32_rna(cospif((float)((b + 2 * st) & 1023) * s));
    rc.w = tf32_rna(cospif((float)((b + 3 * st) & 1023) * s));
    rs.x = tf32_rna(sinpif((float)((b          ) & 1023) * s));
    rs.y = tf32_rna(sinpif((float)((b +     st) & 1023) * s));
    rs.z = tf32_rna(sinpif((float)((b + 2 * st) & 1023) * s));
    rs.w = tf32_rna(sinpif((float)((b + 3 * st) & 1023) * s));
    Bc4[(size_t)t * 32 + q] = rc;
    Bs4[(size_t)t * 32 + q] = rs;
    int be = (2 * r0 + 1) * t, se = 2 * t;
    const float s2 = 1.0f / 256.0f;
    float4 re;
    re.x = tf32_rna(cospif((float)((be          ) & 511) * s2));
    re.y = tf32_rna(cospif((float)((be +     se) & 511) * s2));
    re.z = tf32_rna(cospif((float)((be + 2 * se) & 511) * s2));
    re.w = tf32_rna(cospif((float)((be + 3 * se) & 511) * s2));
    Ce4[(size_t)t * 32 + q] = re;
}

// ---------------------------------------------------------------- fold
// Vectorized fused fold: X -> (S, D, A2, S2) -> 32 tf32 leaves.
// All arithmetic expression trees match R15 bitwise; intermediates that were
// SMEM arrays (A1, SS, MID) now live in registers; all quad reads are LDS.128.
struct FoldOut { float* L[32]; };

__global__ void __launch_bounds__(256) fold_kernel(
    const float* __restrict__ src, FoldOut fo)
{
    __shared__ float X[4096];
    __shared__ float S[1024], D[1024], A2[1024], S2[1024];
    int tid = threadIdx.x;
    size_t row = blockIdx.x;
    const float4* rp = (const float4*)(src + row * ND);

    #pragma unroll
    for (int i = 0; i < 4; i++)
        ((float4*)X)[tid + i * 256] = rp[tid + i * 256];
    __syncthreads();

    // stage 1: each thread computes r = 4*tid .. 4*tid+3 of S, D, A2, S2
    {
        int r0 = tid * 4;
        // A1[j] = X[j] - X[4095-j];  S[r] = A1[2r]+A1[2r+1];  D[r] = A1[2r]-A1[2r+1]
        float4 xa  = *(float4*)&X[2 * r0];
        float4 xb  = *(float4*)&X[2 * r0 + 4];
        float4 xr1 = *(float4*)&X[4088 - 2 * r0];
        float4 xr2 = *(float4*)&X[4092 - 2 * r0];
        float a0 = xa.x - xr2.w, a1 = xa.y - xr2.z;
        float a2 = xa.z - xr2.y, a3 = xa.w - xr2.x;
        float a4 = xb.x - xr1.w, a5 = xb.y - xr1.z;
        float a6 = xb.z - xr1.y, a7 = xb.w - xr1.x;
        float4 sv, dv;
        sv.x = a0 + a1;  dv.x = a0 - a1;
        sv.y = a2 + a3;  dv.y = a2 - a3;
        sv.z = a4 + a5;  dv.z = a4 - a5;
        sv.w = a6 + a7;  dv.w = a6 - a7;
        *(float4*)&S[r0] = sv;
        *(float4*)&D[r0] = dv;
        // SS[j] = X[j] + X[4095-j];  A2[r] = SS[r]-SS[2047-r];  S2[r] = SS[r]+SS[2047-r]
        float4 x1 = *(float4*)&X[r0];
        float4 x2 = *(float4*)&X[4092 - r0];
        float4 x3 = *(float4*)&X[2044 - r0];
        float4 x4 = *(float4*)&X[2048 + r0];
        float ua0 = x1.x + x2.w, ub0 = x3.w + x4.x;
        float ua1 = x1.y + x2.z, ub1 = x3.z + x4.y;
        float ua2 = x1.z + x2.y, ub2 = x3.y + x4.z;
        float ua3 = x1.w + x2.x, ub3 = x3.x + x4.w;
        float4 av, s2v;
        av.x = ua0 - ub0;  s2v.x = ua0 + ub0;
        av.y = ua1 - ub1;  s2v.y = ua1 + ub1;
        av.z = ua2 - ub2;  s2v.z = ua2 + ub2;
        av.w = ua3 - ub3;  s2v.w = ua3 + ub3;
        *(float4*)&A2[r0] = av;
        *(float4*)&S2[r0] = s2v;
    }
    __syncthreads();

    // stage 2: leaves. Threads 0..127 -> mids 0..7 (S, D); 128..255 -> 8..15 (A2, S2).
    int g = tid >> 7;
    int rho = tid & 127;
    size_t ob = row * 128 + rho;
    if (g == 0) {
        // m=0,1 from S forward quads
        float4 A = *(float4*)&S[8 * rho];
        float4 B = *(float4*)&S[8 * rho + 4];
        float p0 = (A.x + A.y) + (A.z + A.w), q0 = (B.x + B.y) + (B.z + B.w);
        float p1 = (A.x + A.y) - (A.z + A.w), q1 = (B.x + B.y) - (B.z + B.w);
        fo.L[0][ob] = tf32_rna(p0 + q0);  fo.L[1][ob] = tf32_rna(p0 - q0);
        fo.L[2][ob] = tf32_rna(p1 + q1);  fo.L[3][ob] = tf32_rna(p1 - q1);
        // m=2,3 from S reversed quads: t = S[1020-4r .. 1023-4r]
        float4 C = *(float4*)&S[1020 - 8 * rho];     // r = 2rho
        float4 E = *(float4*)&S[1016 - 8 * rho];     // r = 2rho+1
        float p2 = (C.z - C.w) + (C.x - C.y), q2 = (E.z - E.w) + (E.x - E.y);
        float p3 = (C.z - C.w) - (C.x - C.y), q3 = (E.z - E.w) - (E.x - E.y);
        fo.L[4][ob] = tf32_rna(p2 + q2);  fo.L[5][ob] = tf32_rna(p2 - q2);
        fo.L[6][ob] = tf32_rna(p3 + q3);  fo.L[7][ob] = tf32_rna(p3 - q3);
        // m=4,5 from D reversed quads: u = D[1020-4r .. 1023-4r]
        float4 F = *(float4*)&D[1020 - 8 * rho];
        float4 G = *(float4*)&D[1016 - 8 * rho];
        float p4 = (F.w + F.z) + (F.y + F.x), q4 = (G.w + G.z) + (G.y + G.x);
        float p5 = (F.w + F.z) - (F.y + F.x), q5 = (G.w + G.z) - (G.y + G.x);
        fo.L[8][ob]  = tf32_rna(p4 + q4);  fo.L[9][ob]  = tf32_rna(p4 - q4);
        fo.L[10][ob] = tf32_rna(p5 + q5);  fo.L[11][ob] = tf32_rna(p5 - q5);
        // m=6,7 from D forward quads: d = D[4r .. 4r+3]
        float4 H = *(float4*)&D[8 * rho];
        float4 I = *(float4*)&D[8 * rho + 4];
        float p6 = (H.y - H.x) + (H.w - H.z), q6 = (I.y - I.x) + (I.w - I.z);
        float p7 = (H.y - H.x) - (H.w - H.z), q7 = (I.y - I.x) - (I.w - I.z);
        fo.L[12][ob] = tf32_rna(p6 + q6);  fo.L[13][ob] = tf32_rna(p6 - q6);
        fo.L[14][ob] = tf32_rna(p7 + q7);  fo.L[15][ob] = tf32_rna(p7 - q7);
    } else {
        // m=8,9 from A2 forward quads
        float4 A = *(float4*)&A2[8 * rho];
        float4 B = *(float4*)&A2[8 * rho + 4];
        float p8 = (A.x + A.y) + (A.z + A.w), q8 = (B.x + B.y) + (B.z + B.w);
        float p9 = (A.x + A.y) - (A.z + A.w), q9 = (B.x + B.y) - (B.z + B.w);
        fo.L[16][ob] = tf32_rna(p8 + q8);  fo.L[17][ob] = tf32_rna(p8 - q8);
        fo.L[18][ob] = tf32_rna(p9 + q9);  fo.L[19][ob] = tf32_rna(p9 - q9);
        // m=10,11 from A2 reversed quads: b = A2[1020-4r .. 1023-4r]
        float4 C = *(float4*)&A2[1020 - 8 * rho];
        float4 E = *(float4*)&A2[1016 - 8 * rho];
        float pa = (C.z - C.w) + (C.x - C.y), qa = (E.z - E.w) + (E.x - E.y);
        float pb = (C.z - C.w) - (C.x - C.y), qb = (E.z - E.w) - (E.x - E.y);
        fo.L[20][ob] = tf32_rna(pa + qa);  fo.L[21][ob] = tf32_rna(pa - qa);
        fo.L[22][ob] = tf32_rna(pb + qb);  fo.L[23][ob] = tf32_rna(pb - qb);
        // m=12,13: w0 = S2[2r]-S2[1023-2r]; w1 = S2[2r+1]-S2[1022-2r]
        float4 Fq = *(float4*)&S2[4 * rho];          // S2[4rho..4rho+3]
        float4 Gq = *(float4*)&S2[1020 - 4 * rho];   // S2[1020-4rho..1023-4rho]
        float w0a = Fq.x - Gq.w, w1a = Fq.y - Gq.z;  // r = 2rho
        float w0b = Fq.z - Gq.y, w1b = Fq.w - Gq.x;  // r = 2rho+1
        float pc = w0a + w1a, qc = w0b + w1b;
        float pd = w0a - w1a, qd = w0b - w1b;
        fo.L[24][ob] = tf32_rna(pc + qc);  fo.L[25][ob] = tf32_rna(pc - qc);
        fo.L[26][ob] = tf32_rna(pd + qd);  fo.L[27][ob] = tf32_rna(pd - qd);
        // m=14: mirror split of MID14; MID14(r) = (S2[r]+S2[1023-r]) + (S2[511-r]+S2[512+r])
        float m14p = (S2[rho] + S2[1023 - rho]) + (S2[511 - rho] + S2[512 + rho]);
        float m14q = (S2[255 - rho] + S2[768 + rho]) + (S2[256 + rho] + S2[767 - rho]);
        fo.L[28][ob] = tf32_rna(m14p + m14q);
        fo.L[29][ob] = tf32_rna(m14p - m14q);
        // m=15: pair split; MID15(r) = (S2[r]+S2[1023-r]) - (S2[511-r]+S2[512+r])
        float m15p = (S2[2 * rho]     + S2[1023 - 2 * rho]) -
                     (S2[511 - 2 * rho] + S2[512 + 2 * rho]);
        float m15q = (S2[2 * rho + 1] + S2[1022 - 2 * rho]) -
                     (S2[510 - 2 * rho] + S2[513 + 2 * rho]);
        fo.L[30][ob] = tf32_rna(m15p + m15q);
        fo.L[31][ob] = tf32_rna(m15p - m15q);
    }
}

// ---------------------------------------------------------------- rotate (R15 validated)
struct RotParams { const float* P[30]; float* out; };

__global__ void __launch_bounds__(256) rotate_kernel(RotParams rp) {
    int tau = blockIdx.y;                             // 0..127
    int c2 = blockIdx.x * 256 + threadIdx.x;          // 0..2047 (float2 cols)
    size_t off = (size_t)tau * 2048 + c2;
    float c4 = cospif((float)(2 * tau + 1) * (1.0f / 1024.0f));
    float s4 = sinpif((float)(2 * tau + 1) * (1.0f / 1024.0f));
    float* out = rp.out;

    float2 PC[7][2], PS[7][2];
    #pragma unroll
    for (int j = 0; j < 7; j++) {
        float2 a = ((const float2*)rp.P[4 * j])[off];
        float2 b = ((const float2*)rp.P[4 * j + 1])[off];
        float2 c = ((const float2*)rp.P[4 * j + 2])[off];
        float2 d = ((const float2*)rp.P[4 * j + 3])[off];
        PC[j][0] = f2c2( c4, a, s4, b);
        PC[j][1] = f2c2(-s4, a, c4, b);
        PS[j][0] = f2c2( c4, c, -s4, d);
        PS[j][1] = f2c2( s4, c,  c4, d);
    }
    {
        float2 e0 = ((const float2*)rp.P[28])[off];
        float2 e1 = ((const float2*)rp.P[29])[off];
        ((float2*)(out + (size_t)(16 * tau + 8) * ND))[c2]         = f2c2( c4, e0, s4, e1);
        ((float2*)(out + (size_t)(16 * (255 - tau) + 8) * ND))[c2] = f2c2(-s4, e0, c4, e1);
    }

    #pragma unroll
    for (int h4 = 0; h4 < 2; h4++) {
        int t3 = h4 ? (255 - tau) : tau;
        float2 p0 = PC[0][h4], q0 = PS[0][h4];
        float2 p1 = PC[1][h4], q1 = PS[1][h4];
        float2 p2 = PC[2][h4], q2 = PS[2][h4];
        float2 p3 = PC[3][h4], q3 = PS[3][h4];
        float2 p4 = PC[4][h4], q4 = PS[4][h4];
        float2 p5 = PC[5][h4], q5 = PS[5][h4];
        float2 p7 = PC[6][h4], q7 = PS[6][h4];

        float c3 = cospif((float)(2 * t3 + 1) * (1.0f / 2048.0f));
        float s3 = sinpif((float)(2 * t3 + 1) * (1.0f / 2048.0f));
        float sg3 = (t3 & 1) ? -1.0f : 1.0f;

        float2 Scc_a = f2c2( c3, p0, s3, q0), Scc_b = f2c2(-s3, p0, c3, q0);
        float2 D1a   = f2c2( c3, p1, s3, q1), D1b   = f2c2(-s3, p1, c3, q1);
        float2 Scd_a = f2s( sg3, D1a),        Scd_b = f2s(-sg3, D1b);
        float2 Sdc_a = f2c2( c3, p2, s3, q2), Sdc_b = f2c2(-s3, p2, c3, q2);
        float2 D3a   = f2c2( c3, p3, s3, q3), D3b   = f2c2(-s3, p3, c3, q3);
        float2 Sdd_a = f2s( sg3, D3a),        Sdd_b = f2s(-sg3, D3b);
        float2 O2c_a = f2c2( c3, p4, s3, q4), O2c_b = f2c2(-s3, p4, c3, q4);
        float2 D5a   = f2c2( c3, p5, s3, q5), D5b   = f2c2(-s3, p5, c3, q5);
        float2 O2d_a = f2s( sg3, D5a),        O2d_b = f2s(-sg3, D5b);

        ((float2*)(out + (size_t)(8 * t3 + 4) * ND))[c2]    = f2c2( c3, p7, s3, q7);
        ((float2*)(out + (size_t)(4092 - 8 * t3) * ND))[c2] = f2c2(-s3, p7, c3, q7);

        #pragma unroll
        for (int h = 0; h < 2; h++) {
            int sg = h ? (511 - t3) : t3;
            float2 vScc = h ? Scc_b : Scc_a, vScd = h ? Scd_b : Scd_a;
            float2 vSdc = h ? Sdc_b : Sdc_a, vSdd = h ? Sdd_b : Sdd_a;
            float2 vO2c = h ? O2c_b : O2c_a, vO2d = h ? O2d_b : O2d_a;
            float c2r = cospif((float)(2 * sg + 1) * (1.0f / 4096.0f));
            float s2r = sinpif((float)(2 * sg + 1) * (1.0f / 4096.0f));
            float c1t = cospif((float)(2 * sg + 1) * (1.0f / 8192.0f));
            float s1t = sinpif((float)(2 * sg + 1) * (1.0f / 8192.0f));
            float c1m = cospif((float)(2047 - 2 * sg) * (1.0f / 8192.0f));
            float s1m = sinpif((float)(2047 - 2 * sg) * (1.0f / 8192.0f));
            float sgn = (sg & 1) ? -1.0f : 1.0f;
            float2 Sct = f2c2( c2r, vScc, s2r, vScd);
            float2 Scm = f2c2(-s2r, vScc, c2r, vScd);
            float2 Drt = f2c2( c2r, vSdc, s2r, vSdd);
            float2 Drm = f2c2(-s2r, vSdc, c2r, vSdd);
            float2 Sdt = f2s( sgn, Drt);
            float2 Sdm = f2s(-sgn, Drm);
            ((float2*)(out + (size_t)(2 * sg + 1) * ND))[c2]    = f2c2( c1t, Sct, s1t, Sdt);
            ((float2*)(out + (size_t)(4095 - 2 * sg) * ND))[c2] = f2c2(-s1t, Sct, c1t, Sdt);
            ((float2*)(out + (size_t)(2047 - 2 * sg) * ND))[c2] = f2c2( c1m, Scm, s1m, Sdm);
            ((float2*)(out + (size_t)(2049 + 2 * sg) * ND))[c2] = f2c2(-s1m, Scm, c1m, Sdm);
            ((float2*)(out + (size_t)(4 * sg + 2) * ND))[c2]    = f2c2( c2r, vO2c, s2r, vO2d);
            ((float2*)(out + (size_t)(4094 - 4 * sg) * ND))[c2] = f2c2(-s2r, vO2c, c2r, vO2d);
        }
    }
}

// ---------------------------------------------------------------- GEMM (R15 proven form)
// 32 uniform branches (M=4096, N=128, K=128), 32 CTAs each.
struct GemmParams {
    const float* A[32];
    const float* B[32];
    float*       O[32];
};

__global__ void __launch_bounds__(256, 2) dct_gemm_kernel(GemmParams p) {
    extern __shared__ __align__(1024) char smem[];
    uint32_t sb = smem_u32(smem);
    int tid = threadIdx.x;
    int wid = tid >> 5, lane = tid & 31;

    int id = blockIdx.x;
    int bi = id >> 5;
    int mb = id & 31;
    int rstride = (bi >= 28 && bi <= 29) ? 32 : 1;
    int roff    = (bi == 29) ? 16 : 0;
    const float* A = p.A[bi];
    const float* B = p.B[bi];
    float* outT = p.O[bi];

    int crow = tid >> 3, cch = tid & 7;
    const float* Ag = A + (size_t)(mb * BM + crow) * KGEMM + cch * 4;
    const float* Bg = B + (size_t)crow * KGEMM + cch * 4;
    uint32_t sA = swz((uint32_t)(crow * 128 + cch * 16));
    const size_t r32 = (size_t)32 * KGEMM;

    auto issue_stage = [&](int k, int s) {
        uint32_t Ab = sb + s * STAGE_BYTES;
        uint32_t Bb = Ab + BM * 128;
        const float* ga = Ag + k * BK;
        const float* gb = Bg + k * BK;
        #pragma unroll
        for (int t = 0; t < 4; t++) {
            uint32_t so = sA + t * 32 * 128;
            cp16(Ab + so, ga + t * r32);
            cp16(Bb + so, gb + t * r32);
        }
    };

    #pragma unroll
    for (int s = 0; s < STAGES - 1; s++) {
        issue_stage(s, s);
        cp_commit();
    }

    int WM = (wid >> 1) * 32;
    int WN = (wid & 1) * 64;

    float d[2][8][4];
    #pragma unroll
    for (int mt = 0; mt < 2; mt++)
        #pragma unroll
        for (int nt = 0; nt < 8; nt++)
            #pragma unroll
            for (int j = 0; j < 4; j++) d[mt][nt][j] = 0.0f;

    uint32_t aoff = (uint32_t)((lane & 15) * 128 + (lane >> 4) * 16);
    uint32_t boff = (uint32_t)(((lane & 7) + ((lane >> 4) << 3)) * 128
                               + ((lane >> 3) & 1) * 16);

    int s = 0;
    for (int k = 0; k < KIT; k++) {
        cp_wait<STAGES - 2>();
        __syncthreads();
        if (k + STAGES - 1 < KIT)
            issue_stage(k + STAGES - 1, (k + STAGES - 1) % STAGES);
        cp_commit();

        uint32_t Ab = sb + s * STAGE_BYTES;
        uint32_t Bb = Ab + BM * 128;

        #pragma unroll
        for (int ks = 0; ks < 4; ks++) {
            uint32_t a0[4], a1r[4], bfr[2][4];
            ldsm4(a0,  Ab + swz((uint32_t)(WM * 128)        + aoff + ks * 32));
            ldsm4(a1r, Ab + swz((uint32_t)((WM + 16) * 128) + aoff + ks * 32));
            ldsm4(bfr[0], Bb + swz((uint32_t)(WN * 128)        + boff + ks * 32));
            ldsm4(bfr[1], Bb + swz((uint32_t)((WN + 16) * 128) + boff + ks * 32));
            #pragma unroll
            for (int nt = 0; nt < 4; nt++) {
                const uint32_t* bb = &bfr[nt >> 1][(nt & 1) * 2];
                mma1688(d[0][nt], a0, bb);
                mma1688(d[1][nt], a1r, bb);
            }
            ldsm4(bfr[0], Bb + swz((uint32_t)((WN + 32) * 128) + boff + ks * 32));
            ldsm4(bfr[1], Bb + swz((uint32_t)((WN + 48) * 128) + boff + ks * 32));
            #pragma unroll
            for (int nt = 0; nt < 4; nt++) {
                const uint32_t* bb = &bfr[nt >> 1][(nt & 1) * 2];
                mma1688(d[0][nt + 4], a0, bb);
                mma1688(d[1][nt + 4], a1r, bb);
            }
        }
        s = (s == STAGES - 1) ? 0 : s + 1;
    }

    // epilogue: transpose through SMEM, coalesced float4 stores
    cp_wait<0>();
    __syncthreads();
    float* T = (float*)smem;
    int g = lane >> 2, tig = lane & 3;
    #pragma unroll
    for (int mt = 0; mt < 2; mt++) {
        #pragma unroll
        for (int nt = 0; nt < 8; nt++) {
            int m = WM + mt * 16 + g;
            int n = WN + nt * 8 + 2 * tig;
            T[n * 132 + m]           = d[mt][nt][0];
            T[(n + 1) * 132 + m]     = d[mt][nt][1];
            T[n * 132 + m + 8]       = d[mt][nt][2];
            T[(n + 1) * 132 + m + 8] = d[mt][nt][3];
        }
    }
    __syncthreads();
    #pragma unroll
    for (int it = 0; it < 16; it++) {
        int i = tid + it * 256;
        int r = i >> 5, c = (i & 31) * 4;
        float4 v = *(float4*)&T[r * 132 + c];
        size_t orow = (size_t)(rstride * r + roff);
        *(float4*)&outT[orow * ND + mb * BM + c] = v;
    }
}

// ---------------------------------------------------------------- host
extern "C" void kernel_launch(void* const* d_in, const int* in_sizes, int n_in,
                              void* d_out, int out_size) {
    void *pBc7, *pBs7, *pCee8, *pYt;
    void *pL[32], *pP[30];
    cudaGetSymbolAddress(&pBc7,  g_Bc7);
    cudaGetSymbolAddress(&pBs7,  g_Bs7);
    cudaGetSymbolAddress(&pCee8, g_Cee8);
    cudaGetSymbolAddress(&pYt,   g_Yt);
    {
        void* base;
        cudaGetSymbolAddress(&base, g_L);
        for (int i = 0; i < 32; i++)
            pL[i] = (char*)base + (size_t)i * ND * 128 * sizeof(float);
        cudaGetSymbolAddress(&base, g_P);
        for (int i = 0; i < 30; i++)
            pP[i] = (char*)base + (size_t)i * 128 * ND * sizeof(float);
    }

    gen_bases_kernel<<<dim3(1, 128), 32>>>((float4*)pBc7, (float4*)pBs7,
                                           (float4*)pCee8);

    cudaFuncSetAttribute(dct_gemm_kernel,
                         cudaFuncAttributeMaxDynamicSharedMemorySize, SMEM_TOTAL);

    FoldOut fo;
    for (int i = 0; i < 32; i++) fo.L[i] = (float*)pL[i];

    GemmParams gp;
    for (int bi = 0; bi < 32; bi++) {
        gp.A[bi] = (const float*)pL[bi];
        int m = bi >> 1, isd = bi & 1;
        const void* Bp;
        if (m == 14)      Bp = isd ? pBc7 : pCee8;
        else if (m == 15) Bp = isd ? pBs7 : pBc7;
        else if ((m & 1) == 0) Bp = isd ? pBs7 : pBc7;
        else                   Bp = isd ? pBc7 : pBs7;
        gp.B[bi] = (const float*)Bp;
    }
    for (int bi = 0; bi < 28; bi++) gp.O[bi] = (float*)pP[bi];
    gp.O[30] = (float*)pP[28];
    gp.O[31] = (float*)pP[29];

    RotParams rp;
    for (int i = 0; i < 30; i++) rp.P[i] = (const float*)pP[i];

    // ---- Pass A: x -> Yt[v][i]
    fold_kernel<<<ND, 256>>>((const float*)d_in[0], fo);
    gp.O[28] = (float*)pYt;  gp.O[29] = (float*)pYt;
    dct_gemm_kernel<<<1024, 256, SMEM_TOTAL>>>(gp);
    rp.out = (float*)pYt;
    rotate_kernel<<<dim3(8, 128), 256>>>(rp);

    // ---- Pass B: Yt -> out[u][v]
    fold_kernel<<<ND, 256>>>((const float*)pYt, fo);
    gp.O[28] = (float*)d_out;  gp.O[29] = (float*)d_out;
    dct_gemm_kernel<<<1024, 256, SMEM_TOTAL>>>(gp);
    rp.out = (float*)d_out;
    rotate_kernel<<<dim3(8, 128), 256>>>(rp);
}